// round 4
// baseline (speedup 1.0000x reference)
#include <cuda_runtime.h>
#include <cuda_bf16.h>

// Problem constants (fixed by the reference)
#define BQ    2
#define NPTS  8192
#define GQ    256
#define XMINF (-35.0f)
#define CELLW (0.2734375f)   // 70/256, exactly representable

// Spatial bucket grid for exact 1-NN
#define GS      16
#define GS3     (GS * GS * GS)
#define CELLSZ  4.25f          // 68/16, exact in fp32
#define INVCELL (1.0f / 4.25f)

#define BT 1024                // build kernel block size
#define PPT 8                  // points per thread in build (8192/1024)

// -------- scratch (device globals; zero-initialized at load; every kernel
// restores its own state so graph replays see identical entry conditions) ----
__device__ int    g_offs  [2 * BQ * (GS3 + 1)];    // exclusive offsets + sentinel
__device__ float4 g_sorted[2 * BQ * NPTS];         // bucketed (x,y,z,orig_idx)
__device__ unsigned long long g_best_x[BQ * NPTS]; // (dist_bits<<32)|argmin_j
__device__ unsigned long long g_best_y[BQ * NPTS]; // (dist_bits<<32)|argmin_i
__device__ int    g_grid[BQ * GQ * GQ];            // ((n+1)<<1)|label, 0 = empty
__device__ double g_sum;
__device__ int    g_vcnt;
__device__ unsigned g_done;

__device__ __forceinline__ int cell_coord(float v) {
    int c = (int)((v + 34.0f) * INVCELL);
    return min(max(c, 0), GS - 1);
}

// ===== build: fused histogram + scan + scatter, one block per (src,b) =====
__global__ void __launch_bounds__(BT)
build_kernel(const float* __restrict__ p_i, const float* __restrict__ p_j) {
    const int combo = blockIdx.x;            // src*BQ + b
    const int src = combo >> 1, b = combo & 1;
    const float* __restrict__ P = (src ? p_j : p_i) + (size_t)b * NPTS * 3;
    const int tid = threadIdx.x;

    __shared__ int   scnt[GS3];              // hist -> cursors
    __shared__ float stage[3 * BT];          // coalesced point staging
    __shared__ int   wsum[32];

    for (int c = tid; c < GS3; c += BT) scnt[c] = 0;

    float px[PPT], py[PPT], pz[PPT];
    #pragma unroll
    for (int ch = 0; ch < PPT; ch++) {
        __syncthreads();
        for (int t = tid; t < 3 * BT; t += BT)
            stage[t] = P[ch * 3 * BT + t];
        __syncthreads();
        px[ch] = stage[tid * 3 + 0];
        py[ch] = stage[tid * 3 + 1];
        pz[ch] = stage[tid * 3 + 2];
        int cell = (cell_coord(pz[ch]) * GS + cell_coord(py[ch])) * GS + cell_coord(px[ch]);
        atomicAdd(&scnt[cell], 1);
    }
    __syncthreads();

    // exclusive block-scan over GS3 counts (4 per thread)
    const int lane = tid & 31, warp = tid >> 5;
    const int c0 = tid * 4;
    int v0 = scnt[c0], v1 = scnt[c0 + 1], v2 = scnt[c0 + 2], v3 = scnt[c0 + 3];
    int s = v0 + v1 + v2 + v3;
    int inc = s;
    #pragma unroll
    for (int o = 1; o < 32; o <<= 1) {
        int x = __shfl_up_sync(0xFFFFFFFFu, inc, o);
        if (lane >= o) inc += x;
    }
    if (lane == 31) wsum[warp] = inc;
    __syncthreads();
    if (warp == 0) {
        int w = wsum[lane];
        #pragma unroll
        for (int o = 1; o < 32; o <<= 1) {
            int x = __shfl_up_sync(0xFFFFFFFFu, w, o);
            if (lane >= o) w += x;
        }
        wsum[lane] = w;
    }
    __syncthreads();
    int excl = inc - s + (warp ? wsum[warp - 1] : 0);
    const int gbase = combo * (GS3 + 1);
    int e0 = excl, e1 = e0 + v0, e2 = e1 + v1, e3 = e2 + v2;
    g_offs[gbase + c0 + 0] = e0;
    g_offs[gbase + c0 + 1] = e1;
    g_offs[gbase + c0 + 2] = e2;
    g_offs[gbase + c0 + 3] = e3;
    __syncthreads();               // everyone done reading counts
    scnt[c0] = e0; scnt[c0 + 1] = e1; scnt[c0 + 2] = e2; scnt[c0 + 3] = e3;
    if (tid == BT - 1) g_offs[gbase + GS3] = NPTS;
    __syncthreads();

    // scatter (cursors in smem)
    float4* __restrict__ S = &g_sorted[combo * NPTS];
    #pragma unroll
    for (int ch = 0; ch < PPT; ch++) {
        int n = ch * BT + tid;
        int cell = (cell_coord(pz[ch]) * GS + cell_coord(py[ch])) * GS + cell_coord(px[ch]);
        int pos = atomicAdd(&scnt[cell], 1);
        S[pos] = make_float4(px[ch], py[ch], pz[ch], __int_as_float(n));
    }
}

// ===== exact 1-NN via expanding L1 ring search =====
// One thread per query (bucket order => warp locality). Packed
// (dist_bits<<32)|orig_j key-min = exact min-dist, first-occurrence tie-break.
// Ring r's L1 lower bound is (r-1)*CELLSZ; strict-greater exit (with margin)
// never skips a potential winner or tie.
__global__ void query_kernel() {
    int t = blockIdx.x * blockDim.x + threadIdx.x;   // [dir][b][q]
    int q = t & (NPTS - 1), b = (t >> 13) & 1, dir = t >> 14;
    int qc = dir * BQ + b;          // query combo (dir0: p_i, dir1: p_j)
    int tc = (1 - dir) * BQ + b;    // target combo

    float4 Q = g_sorted[qc * NPTS + q];
    const float qx = Q.x, qy = Q.y, qz = Q.z;
    const int orig = __float_as_int(Q.w);

    const int* __restrict__ offs = &g_offs[tc * (GS3 + 1)];
    const float4* __restrict__ T = &g_sorted[tc * NPTS];

    const int qcx = cell_coord(qx), qcy = cell_coord(qy), qcz = cell_coord(qz);

    unsigned long long bestkey = ((unsigned long long)0x7F800000u << 32); // +inf

    for (int r = 0; r < GS; r++) {
        if (r >= 1) {
            float bestd = __uint_as_float((unsigned)(bestkey >> 32));
            if ((float)(r - 1) * CELLSZ - 1e-3f > bestd) break;
        }
        int z0 = max(qcz - r, 0), z1 = min(qcz + r, GS - 1);
        int y0 = max(qcy - r, 0), y1 = min(qcy + r, GS - 1);
        int x0 = max(qcx - r, 0), x1 = min(qcx + r, GS - 1);
        for (int cz = z0; cz <= z1; cz++) {
            int az = abs(cz - qcz);
            for (int cy = y0; cy <= y1; cy++) {
                int am = max(az, abs(cy - qcy));
                int rowbase = (cz * GS + cy) * GS;
                if (am == r) {
                    // whole x-run on the shell; cells contiguous -> one range
                    int p0 = offs[rowbase + x0];
                    int p1 = offs[rowbase + x1 + 1];
                    for (int p = p0; p < p1; p++) {
                        float4 tp = T[p];
                        float d = fabsf(qx - tp.x) + fabsf(qy - tp.y);
                        d += fabsf(qz - tp.z);
                        unsigned long long key =
                            ((unsigned long long)__float_as_uint(d) << 32) |
                            (unsigned)__float_as_int(tp.w);
                        if (key < bestkey) bestkey = key;
                    }
                } else {
                    // only the two x-extremes on the shell
                    #pragma unroll
                    for (int sgn = 0; sgn < 2; sgn++) {
                        int cx = sgn ? qcx + r : qcx - r;
                        if (cx < 0 || cx > GS - 1) continue;
                        int c = rowbase + cx;
                        int p0 = offs[c], p1 = offs[c + 1];
                        for (int p = p0; p < p1; p++) {
                            float4 tp = T[p];
                            float d = fabsf(qx - tp.x) + fabsf(qy - tp.y);
                            d += fabsf(qz - tp.z);
                            unsigned long long key =
                                ((unsigned long long)__float_as_uint(d) << 32) |
                                (unsigned)__float_as_int(tp.w);
                            if (key < bestkey) bestkey = key;
                        }
                    }
                }
            }
        }
    }

    (dir ? g_best_y : g_best_x)[b * NPTS + orig] = bestkey;
}

// ===== epilogue: classify, gather p_j, scatter label into grid =====
// Last-write-wins via atomicMax on ((n+1)<<1)|label (0 = empty cell).
__global__ void epilogue_kernel(const float* __restrict__ pj,
                                const float* __restrict__ flow_err,
                                const int*  __restrict__ nf) {
    int t = blockIdx.x * blockDim.x + threadIdx.x; // = b*NPTS + n
    int b = t >> 13;
    int n = t & (NPTS - 1);

    float fe = __ldg(&flow_err[t]);      // independent loads first (MLP)
    int   nfv = __ldg(&nf[t]);
    unsigned long long kx = g_best_x[t];
    unsigned long long ky = g_best_y[t];

    float chx = __uint_as_float((unsigned)(kx >> 32));
    float chy = __uint_as_float((unsigned)(ky >> 32));
    int   jr  = (int)(kx & 0xFFFFFFFFu);

    float rigid = (chx + chy) * 0.5f;          // same op order as reference
    bool  dyn   = fe > rigid;
    int   idx   = dyn ? nfv : jr;
    int   label = dyn ? 1 : 0;

    const float* P = pj + ((size_t)b * NPTS + idx) * 3;
    float px = P[0], py = P[1];

    // IEEE fp32 divide to match XLA exactly (immune to --use_fast_math)
    int gx = (int)__fdiv_rn(px - XMINF, CELLW);
    int gy = (int)__fdiv_rn(py - XMINF, CELLW);
    gx = min(max(gx, 0), GQ - 1);
    gy = min(max(gy, 0), GQ - 1);

    atomicMax(&g_grid[(b * GQ + gx) * GQ + gy], ((n + 1) << 1) | label);
}

// ===== masked cross-entropy + fused finalize (last-block pattern) =====
__global__ void loss_kernel(const float* __restrict__ mos, float* __restrict__ out) {
    int t = blockIdx.x * blockDim.x + threadIdx.x;
    float s = 0.0f;
    int   c = 0;
    {
        int v = g_grid[t];
        if (v > 0) {
            g_grid[t] = 0;                       // restore for next replay
            int label = v & 1;
            int b     = t >> 16;                 // / (GQ*GQ)
            int cell  = t & (GQ * GQ - 1);
            const float* Mb = mos + (size_t)b * 2 * GQ * GQ;
            float m0 = Mb[cell];
            float m1 = Mb[GQ * GQ + cell];
            float lse = fmaxf(m0, m1) + log1pf(__expf(-fabsf(m0 - m1)));
            s = lse - (label ? m1 : m0);         // = -log_softmax[label]
            c = 1;
        }
    }
    #pragma unroll
    for (int o = 16; o > 0; o >>= 1) {
        s += __shfl_down_sync(0xFFFFFFFFu, s, o);
        c += __shfl_down_sync(0xFFFFFFFFu, c, o);
    }
    __shared__ float ss[32];
    __shared__ int   sc[32];
    __shared__ bool  sLast;
    int lane = threadIdx.x & 31, warp = threadIdx.x >> 5;
    int nw = blockDim.x >> 5;
    if (lane == 0) { ss[warp] = s; sc[warp] = c; }
    __syncthreads();
    if (warp == 0) {
        s = (lane < nw) ? ss[lane] : 0.0f;
        c = (lane < nw) ? sc[lane] : 0;
        #pragma unroll
        for (int o = 16; o > 0; o >>= 1) {
            s += __shfl_down_sync(0xFFFFFFFFu, s, o);
            c += __shfl_down_sync(0xFFFFFFFFu, c, o);
        }
        if (lane == 0) {
            if (s != 0.0f) atomicAdd(&g_sum, (double)s);
            if (c)         atomicAdd(&g_vcnt, c);
            __threadfence();
            unsigned d = atomicAdd(&g_done, 1u);
            sLast = (d == gridDim.x - 1);
        }
    }
    __syncthreads();
    if (sLast && threadIdx.x == 0) {
        int cnt = g_vcnt;
        if (cnt < 1) cnt = 1;
        out[0] = (float)(g_sum / (double)cnt);
        g_sum = 0.0; g_vcnt = 0; g_done = 0;     // restore for next replay
    }
}

// -------- launch: 4 graph nodes --------
extern "C" void kernel_launch(void* const* d_in, const int* in_sizes, int n_in,
                              void* d_out, int out_size) {
    const float* p_i  = (const float*)d_in[0]; // (B,N,3)
    const float* mos  = (const float*)d_in[1]; // (B,2,G,G)
    const float* p_j  = (const float*)d_in[2]; // (B,M,3)
    const float* ferr = (const float*)d_in[3]; // (B,N)
    const int*   nf   = (const int*)d_in[4];   // (B,N,1)
    float* out = (float*)d_out;

    build_kernel<<<2 * BQ, BT>>>(p_i, p_j);
    query_kernel<<<(2 * BQ * NPTS) / 256, 256>>>();
    epilogue_kernel<<<(BQ * NPTS) / 256, 256>>>(p_j, ferr, nf);
    loss_kernel<<<(BQ * GQ * GQ) / 1024, 1024>>>(mos, out);
}

// round 5
// speedup vs baseline: 1.0810x; 1.0810x over previous
#include <cuda_runtime.h>
#include <cuda_bf16.h>

// Problem constants (fixed by the reference)
#define BQ    2
#define NPTS  8192
#define GQ    256
#define XMINF (-35.0f)
#define CELLW (0.2734375f)   // 70/256, exactly representable

// Spatial bucket grid for exact 1-NN
#define GS      16
#define GS3     (GS * GS * GS)
#define CELLSZ  4.25f          // 68/16, exact in fp32
#define INVCELL (1.0f / 4.25f)

// -------- scratch (device globals; zero-initialized at load; every kernel
// restores what it consumed, so graph replays see identical entry state) ----
__device__ int    g_ccnt  [2 * BQ * GS3];          // per-cell counts (re-zeroed by scan)
__device__ int    g_offs  [2 * BQ * (GS3 + 1)];    // exclusive offsets + sentinel
__device__ int    g_cursor[2 * BQ * GS3];          // scatter cursors
__device__ int    g_cellid[2 * BQ * NPTS];         // cell id per point
__device__ float4 g_sorted[2 * BQ * NPTS];         // bucketed (x,y,z,orig_idx)
__device__ unsigned long long g_best_x[BQ * NPTS]; // (dist_bits<<32)|argmin_j
__device__ unsigned long long g_best_y[BQ * NPTS]; // (dist_bits<<32)|argmin_i
__device__ int    g_grid[BQ * GQ * GQ];            // ((n+1)<<1)|label, 0 = empty (re-zeroed by loss)
__device__ double g_sum;
__device__ int    g_vcnt;
__device__ unsigned g_done;

__device__ __forceinline__ int cell_coord(float v) {
    int c = (int)((v + 34.0f) * INVCELL);
    return min(max(c, 0), GS - 1);
}

// ===== histogram: count points per cell, remember each point's cell =====
__global__ void hist_kernel(const float* __restrict__ p_i,
                            const float* __restrict__ p_j) {
    int t = blockIdx.x * blockDim.x + threadIdx.x;   // [src][b][n]
    int n = t & (NPTS - 1), b = (t >> 13) & 1, src = t >> 14;
    const float* P = (src ? p_j : p_i) + ((size_t)b * NPTS + n) * 3;
    int cell = (cell_coord(P[2]) * GS + cell_coord(P[1])) * GS + cell_coord(P[0]);
    g_cellid[t] = cell;
    atomicAdd(&g_ccnt[(src * BQ + b) * GS3 + cell], 1);
}

// ===== exclusive scan per combo; writes offs+sentinel, cursors; re-zeroes counts =====
__global__ void scan_kernel() {
    const int combo = blockIdx.x;
    const int base = combo * GS3;
    const int obase = combo * (GS3 + 1);
    const int lane = threadIdx.x & 31, warp = threadIdx.x >> 5;
    __shared__ int wsum[16];

    int v[8]; int s = 0;
    #pragma unroll
    for (int k = 0; k < 8; k++) { v[k] = g_ccnt[base + threadIdx.x * 8 + k]; s += v[k]; }

    int inc = s;
    #pragma unroll
    for (int o = 1; o < 32; o <<= 1) {
        int x = __shfl_up_sync(0xFFFFFFFFu, inc, o);
        if (lane >= o) inc += x;
    }
    if (lane == 31) wsum[warp] = inc;
    __syncthreads();
    if (warp == 0 && lane < 16) {
        int w = wsum[lane];
        #pragma unroll
        for (int o = 1; o < 16; o <<= 1) {
            int x = __shfl_up_sync(0xFFFFu, w, o);
            if (lane >= o) w += x;
        }
        wsum[lane] = w;
    }
    __syncthreads();
    int excl = inc - s + (warp ? wsum[warp - 1] : 0);
    #pragma unroll
    for (int k = 0; k < 8; k++) {
        int idx = threadIdx.x * 8 + k;
        g_offs[obase + idx] = excl;
        g_cursor[base + idx] = excl;
        g_ccnt[base + idx] = 0;          // restore for next replay
        excl += v[k];
    }
    if (threadIdx.x == 0) g_offs[obase + GS3] = NPTS;
}

// ===== scatter points into bucket order =====
__global__ void scatter_kernel(const float* __restrict__ p_i,
                               const float* __restrict__ p_j) {
    int t = blockIdx.x * blockDim.x + threadIdx.x;
    int n = t & (NPTS - 1), b = (t >> 13) & 1, src = t >> 14;
    const float* P = (src ? p_j : p_i) + ((size_t)b * NPTS + n) * 3;
    int cell = g_cellid[t];
    int pos = atomicAdd(&g_cursor[(src * BQ + b) * GS3 + cell], 1);
    g_sorted[(src * BQ + b) * NPTS + pos] = make_float4(P[0], P[1], P[2], __int_as_float(n));
}

// ===== exact 1-NN, 4 lanes per query =====
// Aligned 4-lane groups split candidate cell-rows round-robin; the packed
// (dist_bits<<32)|orig_j key is min-combined across the group via shfl_xor,
// so termination branches are group-uniform. Key-min is order independent:
// exact min-dist, first-occurrence (min-j) tie-break = jnp.argmin semantics.
// Ring r's L1 lower bound is (r-1)*CELLSZ; strict-greater exit (with margin)
// never skips a potential winner or tie.
__global__ void query_kernel() {
    int t = blockIdx.x * blockDim.x + threadIdx.x;
    int sub = t & 3;
    int g = t >> 2;                                  // [dir][b][q]
    int q = g & (NPTS - 1), b = (g >> 13) & 1, dir = g >> 14;
    int qc = dir * BQ + b;          // query combo (dir0: p_i, dir1: p_j)
    int tc = (1 - dir) * BQ + b;    // target combo

    float4 Q = g_sorted[qc * NPTS + q];
    const float qx = Q.x, qy = Q.y, qz = Q.z;
    const int orig = __float_as_int(Q.w);

    const int* __restrict__ offs = &g_offs[tc * (GS3 + 1)];
    const float4* __restrict__ T = &g_sorted[tc * NPTS];

    const int qcx = cell_coord(qx), qcy = cell_coord(qy), qcz = cell_coord(qz);

    unsigned long long bestkey = ((unsigned long long)0x7F800000u << 32); // +inf

    // ---- phase 1: full 3x3x3 box (rings 0+1), rows split across the group ----
    {
        int z0 = max(qcz - 1, 0), z1 = min(qcz + 1, GS - 1);
        int y0 = max(qcy - 1, 0), y1 = min(qcy + 1, GS - 1);
        int x0 = max(qcx - 1, 0), x1 = min(qcx + 1, GS - 1);
        int k = 0;
        for (int cz = z0; cz <= z1; cz++) {
            for (int cy = y0; cy <= y1; cy++) {
                if ((k++ & 3) == sub) {
                    int rowbase = (cz * GS + cy) * GS;
                    int p0 = offs[rowbase + x0];
                    int p1 = offs[rowbase + x1 + 1];
                    for (int p = p0; p < p1; p++) {
                        float4 tp = T[p];
                        float d = fabsf(qx - tp.x) + fabsf(qy - tp.y);
                        d += fabsf(qz - tp.z);
                        unsigned long long key =
                            ((unsigned long long)__float_as_uint(d) << 32) |
                            (unsigned)__float_as_int(tp.w);
                        if (key < bestkey) bestkey = key;
                    }
                }
            }
        }
    }
    // group min (xor 1,2 stays inside the aligned 4-lane group)
    #pragma unroll
    for (int o = 1; o <= 2; o <<= 1) {
        unsigned long long other = __shfl_xor_sync(0xFFFFFFFFu, bestkey, o);
        if (other < bestkey) bestkey = other;
    }

    // ---- phase 2: expanding rings r >= 2, group-uniform termination ----
    for (int r = 2; r < GS; r++) {
        float bestd = __uint_as_float((unsigned)(bestkey >> 32));
        if ((float)(r - 1) * CELLSZ - 1e-3f > bestd) break;

        int z0 = max(qcz - r, 0), z1 = min(qcz + r, GS - 1);
        int y0 = max(qcy - r, 0), y1 = min(qcy + r, GS - 1);
        int x0 = max(qcx - r, 0), x1 = min(qcx + r, GS - 1);
        int k = 0;
        for (int cz = z0; cz <= z1; cz++) {
            int az = abs(cz - qcz);
            for (int cy = y0; cy <= y1; cy++) {
                if ((k++ & 3) != sub) continue;
                int am = max(az, abs(cy - qcy));
                int rowbase = (cz * GS + cy) * GS;
                if (am == r) {
                    int p0 = offs[rowbase + x0];
                    int p1 = offs[rowbase + x1 + 1];
                    for (int p = p0; p < p1; p++) {
                        float4 tp = T[p];
                        float d = fabsf(qx - tp.x) + fabsf(qy - tp.y);
                        d += fabsf(qz - tp.z);
                        unsigned long long key =
                            ((unsigned long long)__float_as_uint(d) << 32) |
                            (unsigned)__float_as_int(tp.w);
                        if (key < bestkey) bestkey = key;
                    }
                } else {
                    #pragma unroll
                    for (int sgn = 0; sgn < 2; sgn++) {
                        int cx = sgn ? qcx + r : qcx - r;
                        if (cx < 0 || cx > GS - 1) continue;
                        int c = rowbase + cx;
                        int p0 = offs[c], p1 = offs[c + 1];
                        for (int p = p0; p < p1; p++) {
                            float4 tp = T[p];
                            float d = fabsf(qx - tp.x) + fabsf(qy - tp.y);
                            d += fabsf(qz - tp.z);
                            unsigned long long key =
                                ((unsigned long long)__float_as_uint(d) << 32) |
                                (unsigned)__float_as_int(tp.w);
                            if (key < bestkey) bestkey = key;
                        }
                    }
                }
            }
        }
        #pragma unroll
        for (int o = 1; o <= 2; o <<= 1) {
            unsigned long long other = __shfl_xor_sync(0xFFFFFFFFu, bestkey, o);
            if (other < bestkey) bestkey = other;
        }
    }

    if (sub == 0)
        (dir ? g_best_y : g_best_x)[b * NPTS + orig] = bestkey;
}

// ===== epilogue: classify, gather p_j, scatter label into grid =====
// Last-write-wins via atomicMax on ((n+1)<<1)|label (0 = empty cell).
__global__ void epilogue_kernel(const float* __restrict__ pj,
                                const float* __restrict__ flow_err,
                                const int*  __restrict__ nf) {
    int t = blockIdx.x * blockDim.x + threadIdx.x; // = b*NPTS + n
    int b = t >> 13;
    int n = t & (NPTS - 1);

    float fe = __ldg(&flow_err[t]);      // independent loads first (MLP)
    int   nfv = __ldg(&nf[t]);
    unsigned long long kx = g_best_x[t];
    unsigned long long ky = g_best_y[t];

    float chx = __uint_as_float((unsigned)(kx >> 32));
    float chy = __uint_as_float((unsigned)(ky >> 32));
    int   jr  = (int)(kx & 0xFFFFFFFFu);

    float rigid = (chx + chy) * 0.5f;          // same op order as reference
    bool  dyn   = fe > rigid;
    int   idx   = dyn ? nfv : jr;
    int   label = dyn ? 1 : 0;

    const float* P = pj + ((size_t)b * NPTS + idx) * 3;
    float px = P[0], py = P[1];

    // IEEE fp32 divide to match XLA exactly (immune to --use_fast_math)
    int gx = (int)__fdiv_rn(px - XMINF, CELLW);
    int gy = (int)__fdiv_rn(py - XMINF, CELLW);
    gx = min(max(gx, 0), GQ - 1);
    gy = min(max(gy, 0), GQ - 1);

    atomicMax(&g_grid[(b * GQ + gx) * GQ + gy], ((n + 1) << 1) | label);
}

// ===== masked cross-entropy + fused finalize (last-block pattern) =====
__global__ void loss_kernel(const float* __restrict__ mos, float* __restrict__ out) {
    int t = blockIdx.x * blockDim.x + threadIdx.x;
    float s = 0.0f;
    int   c = 0;
    {
        int v = g_grid[t];
        if (v > 0) {
            g_grid[t] = 0;                       // restore for next replay
            int label = v & 1;
            int b     = t >> 16;                 // / (GQ*GQ)
            int cell  = t & (GQ * GQ - 1);
            const float* Mb = mos + (size_t)b * 2 * GQ * GQ;
            float m0 = Mb[cell];
            float m1 = Mb[GQ * GQ + cell];
            float lse = fmaxf(m0, m1) + log1pf(__expf(-fabsf(m0 - m1)));
            s = lse - (label ? m1 : m0);         // = -log_softmax[label]
            c = 1;
        }
    }
    #pragma unroll
    for (int o = 16; o > 0; o >>= 1) {
        s += __shfl_down_sync(0xFFFFFFFFu, s, o);
        c += __shfl_down_sync(0xFFFFFFFFu, c, o);
    }
    __shared__ float ss[8];
    __shared__ int   sc[8];
    __shared__ bool  sLast;
    int lane = threadIdx.x & 31, warp = threadIdx.x >> 5;
    if (lane == 0) { ss[warp] = s; sc[warp] = c; }
    __syncthreads();
    if (warp == 0) {
        s = (lane < 8) ? ss[lane] : 0.0f;
        c = (lane < 8) ? sc[lane] : 0;
        #pragma unroll
        for (int o = 4; o > 0; o >>= 1) {
            s += __shfl_down_sync(0xFFFFFFFFu, s, o);
            c += __shfl_down_sync(0xFFFFFFFFu, c, o);
        }
        if (lane == 0) {
            if (s != 0.0f) atomicAdd(&g_sum, (double)s);
            if (c)         atomicAdd(&g_vcnt, c);
            __threadfence();
            unsigned d = atomicAdd(&g_done, 1u);
            sLast = (d == gridDim.x - 1);
        }
    }
    __syncthreads();
    if (sLast && threadIdx.x == 0) {
        int cnt = g_vcnt;
        if (cnt < 1) cnt = 1;
        out[0] = (float)(g_sum / (double)cnt);
        g_sum = 0.0; g_vcnt = 0; g_done = 0;     // restore for next replay
    }
}

// -------- launch: 6 graph nodes --------
extern "C" void kernel_launch(void* const* d_in, const int* in_sizes, int n_in,
                              void* d_out, int out_size) {
    const float* p_i  = (const float*)d_in[0]; // (B,N,3)
    const float* mos  = (const float*)d_in[1]; // (B,2,G,G)
    const float* p_j  = (const float*)d_in[2]; // (B,M,3)
    const float* ferr = (const float*)d_in[3]; // (B,N)
    const int*   nf   = (const int*)d_in[4];   // (B,N,1)
    float* out = (float*)d_out;

    hist_kernel<<<(2 * BQ * NPTS) / 256, 256>>>(p_i, p_j);
    scan_kernel<<<2 * BQ, 512>>>();
    scatter_kernel<<<(2 * BQ * NPTS) / 256, 256>>>(p_i, p_j);
    query_kernel<<<(2 * BQ * NPTS * 4) / 256, 256>>>();
    epilogue_kernel<<<(BQ * NPTS) / 256, 256>>>(p_j, ferr, nf);
    loss_kernel<<<(BQ * GQ * GQ) / 256, 256>>>(mos, out);
}